// round 7
// baseline (speedup 1.0000x reference)
#include <cuda_runtime.h>

// out[row, t] = x[row, t - s]  if 0 <= t - s < T else 0
// rows = 256, T = 160000 (T % 4 == 0), s = shifts[row] - max_shift in [-16000, 16000]
//
// All global reads AND writes are aligned 128-bit, with MLP=4 front-batched
// loads per thread. Shift is row-constant, so source word = out word + D
// (D row-constant) and intra-word offset a is uniform: each thread loads one
// aligned float4; the neighbor word comes from lane+1 via warp shuffle
// (lane 31 loads it directly - L1 hit). Word-level zero predication is exact
// because every aligned word lies entirely inside or outside [0, T).

#define VEC 4
#define THREADS 256
#define WPB (VEC * THREADS)   // 1024 float4 words = 4096 floats per tile

__device__ __forceinline__ float4 shfl_down4(float4 v) {
    float4 r;
    r.x = __shfl_down_sync(0xFFFFFFFFu, v.x, 1);
    r.y = __shfl_down_sync(0xFFFFFFFFu, v.y, 1);
    r.z = __shfl_down_sync(0xFFFFFFFFu, v.z, 1);
    r.w = __shfl_down_sync(0xFFFFFFFFu, v.w, 1);
    return r;
}

__device__ __forceinline__ float4 recombine(float4 lo, float4 hi, int a) {
    switch (a) {   // a is uniform across the block: no divergence
    case 0:  return lo;
    case 1:  return make_float4(lo.y, lo.z, lo.w, hi.x);
    case 2:  return make_float4(lo.z, lo.w, hi.x, hi.y);
    default: return make_float4(lo.w, hi.x, hi.y, hi.z);
    }
}

__global__ void __launch_bounds__(THREADS)
random_shift_kernel(const float4* __restrict__ x4,
                    const int* __restrict__ shifts,
                    float4* __restrict__ out4,
                    int T4, int max_shift) {
    const int row = blockIdx.y;
    const int s = shifts[row] - max_shift;

    const int a = (int)(((unsigned)(-s)) & 3u);   // intra-word offset, row-uniform
    const int D = (-s - a) >> 2;                  // source word = out word + D (exact)

    const int tile0 = blockIdx.x * WPB;
    const size_t base = (size_t)row * (size_t)T4;
    const int lane = threadIdx.x & 31;

    // source words needed: [tile0 + D, tile0 + WPB - 1 + D + 1]
    const bool interior = (tile0 + D >= 0) && (tile0 + WPB + D < T4)
                          && (tile0 + WPB <= T4);

    float4 lo[VEC], hi[VEC];

    if (interior) {
#pragma unroll
        for (int k = 0; k < VEC; ++k) {
            const int wl = tile0 + (int)threadIdx.x + k * THREADS + D;
            lo[k] = __ldg(x4 + base + wl);
        }
#pragma unroll
        for (int k = 0; k < VEC; ++k)
            hi[k] = shfl_down4(lo[k]);
        if (lane == 31) {
#pragma unroll
            for (int k = 0; k < VEC; ++k) {
                const int wl = tile0 + (int)threadIdx.x + k * THREADS + D;
                hi[k] = __ldg(x4 + base + wl + 1);
            }
        }
#pragma unroll
        for (int k = 0; k < VEC; ++k) {
            const int w = tile0 + (int)threadIdx.x + k * THREADS;
            __stcs(out4 + base + w, recombine(lo[k], hi[k], a));
        }
    } else {
        const float4 z = make_float4(0.f, 0.f, 0.f, 0.f);
#pragma unroll
        for (int k = 0; k < VEC; ++k) {
            const int wl = tile0 + (int)threadIdx.x + k * THREADS + D;
            lo[k] = (wl >= 0 && wl < T4) ? __ldg(x4 + base + wl) : z;
        }
#pragma unroll
        for (int k = 0; k < VEC; ++k)
            hi[k] = shfl_down4(lo[k]);
        if (lane == 31) {
#pragma unroll
            for (int k = 0; k < VEC; ++k) {
                const int wh = tile0 + (int)threadIdx.x + k * THREADS + D + 1;
                hi[k] = (wh >= 0 && wh < T4) ? __ldg(x4 + base + wh) : z;
            }
        }
#pragma unroll
        for (int k = 0; k < VEC; ++k) {
            const int w = tile0 + (int)threadIdx.x + k * THREADS;
            if (w < T4)
                __stcs(out4 + base + w, recombine(lo[k], hi[k], a));
        }
    }
}

extern "C" void kernel_launch(void* const* d_in, const int* in_sizes, int n_in,
                              void* d_out, int out_size) {
    const float4* x4     = (const float4*)d_in[0];
    const int*    shifts = (const int*)d_in[1];
    float4*       out4   = (float4*)d_out;

    const int rows = in_sizes[1];            // B*M = 256
    const int T    = in_sizes[0] / rows;     // 160000
    const int T4   = T / 4;                  // 40000
    const int max_shift = T / 10;            // 16000

    dim3 grid((T4 + WPB - 1) / WPB, rows);   // (40, 256)
    random_shift_kernel<<<grid, THREADS>>>(x4, shifts, out4, T4, max_shift);
}